// round 10
// baseline (speedup 1.0000x reference)
#include <cuda_runtime.h>
#include <math.h>
#include <stdint.h>

#define NN 100000
#define NE 1600000
#define NG 1000

// ---------------- scratch (device globals: allocation-free rule) ----------------
__device__ __align__(16) float g_deg[NN];
__device__ __align__(16) float g_dis[NN];
__device__ __align__(16) float g_h0[NN * 128];
__device__ __align__(16) float g_c1[NN * 64];   // dis * (h0 @ bases1^T)
__device__ __align__(16) float g_t1[NN * 64];   // scatter accumulator
__device__ __align__(16) float g_w1[NN * 32];   // h0 @ comb1^T + b
__device__ __align__(16) float g_h1[NN * 128];
__device__ __align__(16) float g_c2[NN * 32];
__device__ __align__(16) float g_t2[NN * 32];
__device__ __align__(16) float g_w2[NN * 32];

__device__ __forceinline__ float elu_f(float v) { return v > 0.f ? v : expm1f(v); }

__device__ __forceinline__ uint32_t f2tf32(float f) {
    uint32_t r;
    asm("cvt.rna.tf32.f32 %0, %1;" : "=r"(r) : "f"(f));
    return r;
}
__device__ __forceinline__ float u2f(uint32_t u) { return __uint_as_float(u); }
__device__ __forceinline__ uint32_t f2u(float f) { return __float_as_uint(f); }

// ---------------- init: zero scatter buffers, deg = 1 (self-loop) ----------------
__global__ void k_init() {
    int i = blockIdx.x * blockDim.x + threadIdx.x;
    float4 z = make_float4(0.f, 0.f, 0.f, 0.f);
    if (i < NN * 16) ((float4*)g_t1)[i] = z;
    if (i < NN * 8)  ((float4*)g_t2)[i] = z;
    if (i < NN)      g_deg[i] = 1.0f;
}

__global__ void k_deg(const int* __restrict__ ei) {
    int e = blockIdx.x * blockDim.x + threadIdx.x;
    if (e < NE) atomicAdd(&g_deg[ei[NE + e]], 1.0f);
}

__global__ void k_dis() {
    int i = blockIdx.x * blockDim.x + threadIdx.x;
    if (i < NN) g_dis[i] = rsqrtf(g_deg[i]);
}

// ============ k_nfc_tc: TF32 tensor-core GEMM, 48KB static smem exactly ============
// h0 = elu(x @ nfc_w^T + nfc_b), x:[100k,64], w:[128,64].
// Block: 128 threads = 4 warps; 64 nodes/block (one m16 tile per warp).
// A: XOR-swizzled (float4 idx c ^ (r&15)) -> 16KB, conflict-free scalar frags.
// W: raw float2 {w[k], w[k+4]} per lane in b-frag order -> 32KB; hi/lo split in regs.
// 3xTF32 split (hi*hi + hi*lo + lo*hi) for fp32-level accuracy.
__global__ __launch_bounds__(128) void k_nfc_tc(const float* __restrict__ x,
                                                const float* __restrict__ w,
                                                const float* __restrict__ b) {
    constexpr int K = 64, KT = 8, NT = 16;
    __shared__ float sA[64 * 64];            // 16384 B
    __shared__ float2 sW[NT * KT * 32];      // 32768 B  -> 49152 B total static

    int tid = threadIdx.x;
    int base = blockIdx.x * 64;

    // stage A with XOR swizzle on float4 index
    for (int i = tid; i < 64 * 16; i += 128) {
        int r = i >> 4, c = i & 15;
        int node = base + r; if (node >= NN) node = NN - 1;
        float4 v = __ldg((const float4*)(x + (size_t)node * K) + c);
        *(float4*)(sA + r * 64 + ((c ^ (r & 15)) << 2)) = v;
    }
    // stage W raw in b-fragment order: lane t of (nt,kt) holds {W[n][k], W[n][k+4]}
    for (int i = tid; i < NT * KT * 32; i += 128) {
        int nt = i >> 8;
        int kt = (i >> 5) & 7;
        int t = i & 31;
        int g = t >> 2, q = t & 3;
        int n = nt * 8 + g;
        sW[(nt * KT + kt) * 32 + t] =
            make_float2(__ldg(w + n * K + kt * 8 + q), __ldg(w + n * K + kt * 8 + q + 4));
    }
    __syncthreads();

    int wid = tid >> 5, lane = tid & 31;
    int g = lane >> 2, q = lane & 3;
    int r0 = wid * 16 + g;        // local row for a0/a2
    int r1 = r0 + 8;              // local row for a1/a3
    int n0 = base + r0;
    int n1 = base + r1;
    bool v0 = n0 < NN, v1 = n1 < NN;

#pragma unroll 1
    for (int ng = 0; ng < 4; ++ng) {
        float acc[4][4];
#pragma unroll
        for (int j = 0; j < 4; ++j) {
            int col = (ng * 4 + j) * 8 + 2 * q;
            float b0 = __ldg(b + col);
            float b1 = __ldg(b + col + 1);
            acc[j][0] = b0; acc[j][1] = b1; acc[j][2] = b0; acc[j][3] = b1;
        }
#pragma unroll
        for (int kt = 0; kt < KT; ++kt) {
            // swizzled scalar reads (conflict-free; see header comment)
            float a0 = sA[r0 * 64 + (((2 * kt)     ^ (r0 & 15)) << 2) + q];
            float a1 = sA[r1 * 64 + (((2 * kt)     ^ (r1 & 15)) << 2) + q];
            float a2 = sA[r0 * 64 + (((2 * kt + 1) ^ (r0 & 15)) << 2) + q];
            float a3 = sA[r1 * 64 + (((2 * kt + 1) ^ (r1 & 15)) << 2) + q];
            uint32_t ah0 = f2tf32(a0), al0 = f2tf32(a0 - u2f(ah0));
            uint32_t ah1 = f2tf32(a1), al1 = f2tf32(a1 - u2f(ah1));
            uint32_t ah2 = f2tf32(a2), al2 = f2tf32(a2 - u2f(ah2));
            uint32_t ah3 = f2tf32(a3), al3 = f2tf32(a3 - u2f(ah3));
#pragma unroll
            for (int j = 0; j < 4; ++j) {
                float2 bb = sW[((ng * 4 + j) * KT + kt) * 32 + lane];
                uint32_t bh0 = f2tf32(bb.x), bl0 = f2tf32(bb.x - u2f(f2tf32(bb.x)));
                uint32_t bh1 = f2tf32(bb.y), bl1 = f2tf32(bb.y - u2f(f2tf32(bb.y)));
                asm volatile(
                    "mma.sync.aligned.m16n8k8.row.col.f32.tf32.tf32.f32 "
                    "{%0,%1,%2,%3},{%4,%5,%6,%7},{%8,%9},{%0,%1,%2,%3};"
                    : "+f"(acc[j][0]), "+f"(acc[j][1]), "+f"(acc[j][2]), "+f"(acc[j][3])
                    : "r"(ah0), "r"(ah1), "r"(ah2), "r"(ah3), "r"(bh0), "r"(bh1));
                asm volatile(
                    "mma.sync.aligned.m16n8k8.row.col.f32.tf32.tf32.f32 "
                    "{%0,%1,%2,%3},{%4,%5,%6,%7},{%8,%9},{%0,%1,%2,%3};"
                    : "+f"(acc[j][0]), "+f"(acc[j][1]), "+f"(acc[j][2]), "+f"(acc[j][3])
                    : "r"(ah0), "r"(ah1), "r"(ah2), "r"(ah3), "r"(bl0), "r"(bl1));
                asm volatile(
                    "mma.sync.aligned.m16n8k8.row.col.f32.tf32.tf32.f32 "
                    "{%0,%1,%2,%3},{%4,%5,%6,%7},{%8,%9},{%0,%1,%2,%3};"
                    : "+f"(acc[j][0]), "+f"(acc[j][1]), "+f"(acc[j][2]), "+f"(acc[j][3])
                    : "r"(al0), "r"(al1), "r"(al2), "r"(al3), "r"(bh0), "r"(bh1));
            }
        }
#pragma unroll
        for (int j = 0; j < 4; ++j) {
            int col = (ng * 4 + j) * 8 + 2 * q;
            if (v0) *(float2*)(g_h0 + (size_t)n0 * 128 + col) =
                make_float2(elu_f(acc[j][0]), elu_f(acc[j][1]));
            if (v1) *(float2*)(g_h0 + (size_t)n1 * 128 + col) =
                make_float2(elu_f(acc[j][2]), elu_f(acc[j][3]));
        }
    }
}

// ---------------- proj1 (R6 proven): c1 = dis*(h0@bases1^T)[64], w1 = h0@comb1^T+cb[32] ----------------
__global__ __launch_bounds__(128) void k_proj1(const float* __restrict__ bw,
                                               const float* __restrict__ cw,
                                               const float* __restrict__ cb) {
    __shared__ float Ws[96 * 128];  // 48KB
    for (int i = threadIdx.x; i < 64 * 128; i += 128) Ws[i] = bw[i];
    for (int i = threadIdx.x; i < 32 * 128; i += 128) Ws[64 * 128 + i] = cw[i];
    __syncthreads();
    int n0 = blockIdx.x * 256 + threadIdx.x;
    int n1 = n0 + 128;
    bool v1 = n1 < NN;
    if (n0 >= NN) return;
    if (!v1) n1 = n0;
    const float4* xp0 = (const float4*)(g_h0 + (size_t)n0 * 128);
    const float4* xp1 = (const float4*)(g_h0 + (size_t)n1 * 128);
    float d0 = g_dis[n0], d1 = g_dis[n1];
#pragma unroll 1
    for (int oc = 0; oc < 6; ++oc) {
        float acc[2][16];
#pragma unroll
        for (int o = 0; o < 16; ++o) {
            float bb = (oc < 4) ? 0.f : __ldg(cb + (oc - 4) * 16 + o);
            acc[0][o] = bb; acc[1][o] = bb;
        }
#pragma unroll 4
        for (int kc = 0; kc < 32; ++kc) {
            float4 x0 = __ldg(xp0 + kc);
            float4 x1 = __ldg(xp1 + kc);
#pragma unroll
            for (int o = 0; o < 16; ++o) {
                float4 wv = *(const float4*)&Ws[(oc * 16 + o) * 128 + kc * 4];
                acc[0][o] = fmaf(x0.x, wv.x, acc[0][o]);
                acc[0][o] = fmaf(x0.y, wv.y, acc[0][o]);
                acc[0][o] = fmaf(x0.z, wv.z, acc[0][o]);
                acc[0][o] = fmaf(x0.w, wv.w, acc[0][o]);
                acc[1][o] = fmaf(x1.x, wv.x, acc[1][o]);
                acc[1][o] = fmaf(x1.y, wv.y, acc[1][o]);
                acc[1][o] = fmaf(x1.z, wv.z, acc[1][o]);
                acc[1][o] = fmaf(x1.w, wv.w, acc[1][o]);
            }
        }
        if (oc < 4) {
            float* o0 = g_c1 + (size_t)n0 * 64 + oc * 16;
            float* o1 = g_c1 + (size_t)n1 * 64 + oc * 16;
#pragma unroll
            for (int o = 0; o < 16; ++o) o0[o] = d0 * acc[0][o];
            if (v1) {
#pragma unroll
                for (int o = 0; o < 16; ++o) o1[o] = d1 * acc[1][o];
            }
        } else {
            float* o0 = g_w1 + (size_t)n0 * 32 + (oc - 4) * 16;
            float* o1 = g_w1 + (size_t)n1 * 32 + (oc - 4) * 16;
#pragma unroll
            for (int o = 0; o < 16; ++o) o0[o] = acc[0][o];
            if (v1) {
#pragma unroll
                for (int o = 0; o < 16; ++o) o1[o] = acc[1][o];
            }
        }
    }
}

// ---------------- proj2 (R6 proven): c2 = dis*(h1@bases2^T)[32], w2 = h1@comb2^T+cb[32] ----------------
__global__ __launch_bounds__(128) void k_proj2(const float* __restrict__ bw,
                                               const float* __restrict__ cw,
                                               const float* __restrict__ cb) {
    __shared__ float Ws[64 * 128];  // 32KB
    for (int i = threadIdx.x; i < 32 * 128; i += 128) Ws[i] = bw[i];
    for (int i = threadIdx.x; i < 32 * 128; i += 128) Ws[32 * 128 + i] = cw[i];
    __syncthreads();
    int n0 = blockIdx.x * 256 + threadIdx.x;
    int n1 = n0 + 128;
    bool v1 = n1 < NN;
    if (n0 >= NN) return;
    if (!v1) n1 = n0;
    const float4* xp0 = (const float4*)(g_h1 + (size_t)n0 * 128);
    const float4* xp1 = (const float4*)(g_h1 + (size_t)n1 * 128);
    float d0 = g_dis[n0], d1 = g_dis[n1];
#pragma unroll 1
    for (int oc = 0; oc < 4; ++oc) {
        float acc[2][16];
#pragma unroll
        for (int o = 0; o < 16; ++o) {
            float bb = (oc < 2) ? 0.f : __ldg(cb + (oc - 2) * 16 + o);
            acc[0][o] = bb; acc[1][o] = bb;
        }
#pragma unroll 4
        for (int kc = 0; kc < 32; ++kc) {
            float4 x0 = __ldg(xp0 + kc);
            float4 x1 = __ldg(xp1 + kc);
#pragma unroll
            for (int o = 0; o < 16; ++o) {
                float4 wv = *(const float4*)&Ws[(oc * 16 + o) * 128 + kc * 4];
                acc[0][o] = fmaf(x0.x, wv.x, acc[0][o]);
                acc[0][o] = fmaf(x0.y, wv.y, acc[0][o]);
                acc[0][o] = fmaf(x0.z, wv.z, acc[0][o]);
                acc[0][o] = fmaf(x0.w, wv.w, acc[0][o]);
                acc[1][o] = fmaf(x1.x, wv.x, acc[1][o]);
                acc[1][o] = fmaf(x1.y, wv.y, acc[1][o]);
                acc[1][o] = fmaf(x1.z, wv.z, acc[1][o]);
                acc[1][o] = fmaf(x1.w, wv.w, acc[1][o]);
            }
        }
        if (oc < 2) {
            float* o0 = g_c2 + (size_t)n0 * 32 + oc * 16;
            float* o1 = g_c2 + (size_t)n1 * 32 + oc * 16;
#pragma unroll
            for (int o = 0; o < 16; ++o) o0[o] = d0 * acc[0][o];
            if (v1) {
#pragma unroll
                for (int o = 0; o < 16; ++o) o1[o] = d1 * acc[1][o];
            }
        } else {
            float* o0 = g_w2 + (size_t)n0 * 32 + (oc - 2) * 16;
            float* o1 = g_w2 + (size_t)n1 * 32 + (oc - 2) * 16;
#pragma unroll
            for (int o = 0; o < 16; ++o) o0[o] = acc[0][o];
            if (v1) {
#pragma unroll
                for (int o = 0; o < 16; ++o) o1[o] = acc[1][o];
            }
        }
    }
}

// ---------------- edge scatter: t[dst] += c[src]  (vector L2 atomics) ----------------
__device__ __forceinline__ void red_add_v4(float4* p, float4 v) {
    asm volatile("red.global.add.v4.f32 [%0], {%1, %2, %3, %4};"
                 :: "l"(p), "f"(v.x), "f"(v.y), "f"(v.z), "f"(v.w) : "memory");
}

__global__ void k_scatter1(const int* __restrict__ ei) {
    int idx = blockIdx.x * blockDim.x + threadIdx.x;
    if (idx >= NE * 16) return;
    int e = idx >> 4, q = idx & 15;
    int s = __ldg(ei + e);
    int d = __ldg(ei + NE + e);
    float4 v = __ldg((const float4*)g_c1 + (size_t)s * 16 + q);
    red_add_v4((float4*)g_t1 + (size_t)d * 16 + q, v);
}

__global__ void k_scatter2(const int* __restrict__ ei) {
    int idx = blockIdx.x * blockDim.x + threadIdx.x;
    if (idx >= NE * 8) return;
    int e = idx >> 3, q = idx & 7;
    int s = __ldg(ei + e);
    int d = __ldg(ei + NE + e);
    float4 v = __ldg((const float4*)g_c2 + (size_t)s * 8 + q);
    red_add_v4((float4*)g_t2 + (size_t)d * 8 + q, v);
}

// ---------------- combine conv1: h1 = elu(einsum(w1, dis*(t1+c1)) + bias) ----------------
__global__ __launch_bounds__(128) void k_comb1(const float* __restrict__ bias) {
    int node = blockIdx.x * 128 + threadIdx.x;
    if (node >= NN) return;
    float d = g_dis[node];
    float agg[64];
#pragma unroll
    for (int i = 0; i < 16; ++i) {
        float4 tv = ((const float4*)g_t1)[(size_t)node * 16 + i];
        float4 cv = ((const float4*)g_c1)[(size_t)node * 16 + i];
        agg[4 * i + 0] = d * (tv.x + cv.x);
        agg[4 * i + 1] = d * (tv.y + cv.y);
        agg[4 * i + 2] = d * (tv.z + cv.z);
        agg[4 * i + 3] = d * (tv.w + cv.w);
    }
    float wv[32];
#pragma unroll
    for (int i = 0; i < 8; ++i) {
        float4 v = ((const float4*)g_w1)[(size_t)node * 8 + i];
        wv[4 * i] = v.x; wv[4 * i + 1] = v.y; wv[4 * i + 2] = v.z; wv[4 * i + 3] = v.w;
    }
    float* outp = g_h1 + (size_t)node * 128;
#pragma unroll
    for (int h = 0; h < 8; ++h) {
#pragma unroll
        for (int f = 0; f < 16; ++f) {
            float s = wv[h * 4 + 0] * agg[f]
                    + wv[h * 4 + 1] * agg[16 + f]
                    + wv[h * 4 + 2] * agg[32 + f]
                    + wv[h * 4 + 3] * agg[48 + f];
            outp[h * 16 + f] = elu_f(s + __ldg(bias + h * 16 + f));
        }
    }
}

// ---------------- combine conv2 + ELU + L2 normalize -> hout ----------------
__global__ __launch_bounds__(128) void k_comb2(const float* __restrict__ bias,
                                               float* __restrict__ hout) {
    int node = blockIdx.x * 128 + threadIdx.x;
    if (node >= NN) return;
    float d = g_dis[node];
    float agg[32];
#pragma unroll
    for (int i = 0; i < 8; ++i) {
        float4 tv = ((const float4*)g_t2)[(size_t)node * 8 + i];
        float4 cv = ((const float4*)g_c2)[(size_t)node * 8 + i];
        agg[4 * i + 0] = d * (tv.x + cv.x);
        agg[4 * i + 1] = d * (tv.y + cv.y);
        agg[4 * i + 2] = d * (tv.z + cv.z);
        agg[4 * i + 3] = d * (tv.w + cv.w);
    }
    float wv[32];
#pragma unroll
    for (int i = 0; i < 8; ++i) {
        float4 v = ((const float4*)g_w2)[(size_t)node * 8 + i];
        wv[4 * i] = v.x; wv[4 * i + 1] = v.y; wv[4 * i + 2] = v.z; wv[4 * i + 3] = v.w;
    }
    float tmp[64];
    float ss = 0.f;
#pragma unroll
    for (int h = 0; h < 8; ++h) {
#pragma unroll
        for (int f = 0; f < 8; ++f) {
            float s = wv[h * 4 + 0] * agg[f]
                    + wv[h * 4 + 1] * agg[8 + f]
                    + wv[h * 4 + 2] * agg[16 + f]
                    + wv[h * 4 + 3] * agg[24 + f];
            float v = elu_f(s + __ldg(bias + h * 8 + f));
            tmp[h * 8 + f] = v;
            ss = fmaf(v, v, ss);
        }
    }
    float sc = 1.0f / fmaxf(sqrtf(ss), 1e-12f);
    float4* op = (float4*)(hout + (size_t)node * 64);
#pragma unroll
    for (int i = 0; i < 16; ++i)
        op[i] = make_float4(tmp[4 * i] * sc, tmp[4 * i + 1] * sc,
                            tmp[4 * i + 2] * sc, tmp[4 * i + 3] * sc);
}

// ---------------- fused per-graph: sum-pool, attention softmax, z_a, z_c ----------------
__global__ __launch_bounds__(128) void k_graph(const float* __restrict__ h,
                                               const float* __restrict__ z_e,
                                               const float* __restrict__ aw,
                                               const float* __restrict__ ab,
                                               const float* __restrict__ fcg_w,
                                               const float* __restrict__ fcg_b,
                                               const float* __restrict__ fccg_w,
                                               const float* __restrict__ fccg_b,
                                               float* __restrict__ za,
                                               float* __restrict__ zc) {
    int g = blockIdx.x;
    int t = threadIdx.x;
    __shared__ float sh[100 * 64];
    __shared__ float slog[100];
    __shared__ float sred[4];
    __shared__ float sp_hs[128];
    __shared__ float sp_zc[128];
    __shared__ float szdot, sm, sdenom;

    const float* hg = h + (size_t)g * 100 * 64;
    for (int i = t; i < 6400; i += 128) sh[i] = hg[i];

    if (t < 32) {
        float v = __ldg(z_e + g * 32 + t) * __ldg(aw + 64 + t);
#pragma unroll
        for (int o = 16; o; o >>= 1) v += __shfl_xor_sync(0xffffffff, v, o);
        if (t == 0) szdot = v;
    }
    __syncthreads();

    int w = t >> 5, l = t & 31;
    {
        float a0 = __ldg(aw + l);
        float a1 = __ldg(aw + 32 + l);
        float bb = __ldg(ab);
        for (int n = w; n < 100; n += 4) {
            float p = sh[n * 64 + l] * a0 + sh[n * 64 + 32 + l] * a1;
#pragma unroll
            for (int o = 16; o; o >>= 1) p += __shfl_xor_sync(0xffffffff, p, o);
            if (l == 0) slog[n] = p + szdot + bb + 1e-16f;
        }
    }
    __syncthreads();

    float m = -INFINITY;
    if (t < 100) m = slog[t];
#pragma unroll
    for (int o = 16; o; o >>= 1) m = fmaxf(m, __shfl_xor_sync(0xffffffff, m, o));
    if (l == 0) sred[w] = m;
    __syncthreads();
    if (t == 0) sm = fmaxf(fmaxf(sred[0], sred[1]), fmaxf(sred[2], sred[3]));
    __syncthreads();

    float ssum = 0.f;
    if (t < 100) {
        float e = expf(slog[t] - sm);
        slog[t] = e;
        ssum = e;
    }
#pragma unroll
    for (int o = 16; o; o >>= 1) ssum += __shfl_xor_sync(0xffffffff, ssum, o);
    if (l == 0) sred[w] = ssum;
    __syncthreads();
    if (t == 0) sdenom = sred[0] + sred[1] + sred[2] + sred[3] + 1e-16f;
    __syncthreads();

    float inv = 1.0f / sdenom;
    int f = t & 63, half = t >> 6;
    float hs = 0.f, zcv = 0.f;
    for (int n = half * 50; n < half * 50 + 50; ++n) {
        float hv = sh[n * 64 + f];
        hs += hv;
        zcv = fmaf(slog[n], hv, zcv);
    }
    sp_hs[t] = hs;
    sp_zc[t] = zcv * inv;
    __syncthreads();
    if (t < 64) {
        sp_hs[t] = sp_hs[t] + sp_hs[t + 64];
        sp_zc[t] = sp_zc[t] + sp_zc[t + 64];
    }
    __syncthreads();

    if (t < 64) {
        float acc = __ldg(fcg_b + t);
        const float* wr = fcg_w + t * 64;
#pragma unroll 8
        for (int k = 0; k < 64; ++k) acc = fmaf(sp_hs[k], __ldg(wr + k), acc);
        za[(size_t)g * 64 + t] = acc;
    } else {
        int ff = t - 64;
        float acc = __ldg(fccg_b + ff);
        const float* wr = fccg_w + ff * 64;
#pragma unroll 8
        for (int k = 0; k < 64; ++k) acc = fmaf(sp_zc[k], __ldg(wr + k), acc);
        zc[(size_t)g * 64 + ff] = acc;
    }
}

// ---------------- launch ----------------
extern "C" void kernel_launch(void* const* d_in, const int* in_sizes, int n_in,
                              void* d_out, int out_size) {
    const float* x        = (const float*)d_in[0];
    const int*   ei       = (const int*)d_in[1];
    const float* z_e      = (const float*)d_in[4];
    const float* nfc_w    = (const float*)d_in[5];
    const float* nfc_b    = (const float*)d_in[6];
    const float* gc1_bw   = (const float*)d_in[7];
    const float* gc1_cw   = (const float*)d_in[8];
    const float* gc1_cb   = (const float*)d_in[9];
    const float* gc1_bias = (const float*)d_in[10];
    const float* gc2_bw   = (const float*)d_in[11];
    const float* gc2_cw   = (const float*)d_in[12];
    const float* gc2_cb   = (const float*)d_in[13];
    const float* gc2_bias = (const float*)d_in[14];
    const float* attn_w   = (const float*)d_in[15];
    const float* attn_b   = (const float*)d_in[16];
    const float* fcg_w    = (const float*)d_in[17];
    const float* fcg_b    = (const float*)d_in[18];
    const float* fccg_w   = (const float*)d_in[19];
    const float* fccg_b   = (const float*)d_in[20];

    float* out   = (float*)d_out;
    float* za    = out;
    float* zc    = out + NG * 64;
    float* hout  = out + 2 * NG * 64;

    int gemmBlocks = (NN + 255) / 256;   // 391, 2 nodes/thread (proj kernels)
    int tcBlocks   = (NN + 63) / 64;     // 1563, 64 nodes/block (tc nfc)
    int nodeBlocks = (NN + 127) / 128;

    k_init<<<(NN * 16 + 255) / 256, 256>>>();
    k_deg<<<(NE + 255) / 256, 256>>>(ei);
    k_dis<<<(NN + 255) / 256, 256>>>();
    k_nfc_tc<<<tcBlocks, 128>>>(x, nfc_w, nfc_b);
    k_proj1<<<gemmBlocks, 128>>>(gc1_bw, gc1_cw, gc1_cb);
    k_scatter1<<<(NE * 16) / 256, 256>>>(ei);
    k_comb1<<<nodeBlocks, 128>>>(gc1_bias);
    k_proj2<<<gemmBlocks, 128>>>(gc2_bw, gc2_cw, gc2_cb);
    k_scatter2<<<(NE * 8) / 256, 256>>>(ei);
    k_comb2<<<nodeBlocks, 128>>>(gc2_bias, hout);
    k_graph<<<NG, 128>>>(hout, z_e, attn_w, attn_b, fcg_w, fcg_b,
                         fccg_w, fccg_b, za, zc);
}

// round 14
// speedup vs baseline: 1.0256x; 1.0256x over previous
#include <cuda_runtime.h>
#include <math.h>
#include <stdint.h>

#define NN 100000
#define NE 1600000
#define NG 1000

// ---------------- scratch (device globals: allocation-free rule) ----------------
__device__ __align__(16) float g_deg[NN];
__device__ __align__(16) float g_dis[NN];
__device__ __align__(16) float g_h0[NN * 128];
__device__ __align__(16) float g_c1[NN * 64];   // dis * (h0 @ bases1^T)
__device__ __align__(16) float g_t1[NN * 64];   // scatter accumulator
__device__ __align__(16) float g_w1[NN * 32];   // h0 @ comb1^T + b
__device__ __align__(16) float g_h1[NN * 128];
__device__ __align__(16) float g_c2[NN * 32];
__device__ __align__(16) float g_t2[NN * 32];
__device__ __align__(16) float g_w2[NN * 32];

__device__ __forceinline__ float elu_f(float v) { return v > 0.f ? v : expm1f(v); }

__device__ __forceinline__ uint32_t f2tf32(float f) {
    uint32_t r;
    asm("cvt.rna.tf32.f32 %0, %1;" : "=r"(r) : "f"(f));
    return r;
}
__device__ __forceinline__ float u2f(uint32_t u) { return __uint_as_float(u); }

#define MMA3(ACC, AH0, AH1, AH2, AH3, AL0, AL1, AL2, AL3, BH0, BH1, BL0, BL1)          \
    asm volatile(                                                                       \
        "mma.sync.aligned.m16n8k8.row.col.f32.tf32.tf32.f32 "                           \
        "{%0,%1,%2,%3},{%4,%5,%6,%7},{%8,%9},{%0,%1,%2,%3};"                            \
        : "+f"(ACC[0]), "+f"(ACC[1]), "+f"(ACC[2]), "+f"(ACC[3])                        \
        : "r"(AH0), "r"(AH1), "r"(AH2), "r"(AH3), "r"(BH0), "r"(BH1));                  \
    asm volatile(                                                                       \
        "mma.sync.aligned.m16n8k8.row.col.f32.tf32.tf32.f32 "                           \
        "{%0,%1,%2,%3},{%4,%5,%6,%7},{%8,%9},{%0,%1,%2,%3};"                            \
        : "+f"(ACC[0]), "+f"(ACC[1]), "+f"(ACC[2]), "+f"(ACC[3])                        \
        : "r"(AH0), "r"(AH1), "r"(AH2), "r"(AH3), "r"(BL0), "r"(BL1));                  \
    asm volatile(                                                                       \
        "mma.sync.aligned.m16n8k8.row.col.f32.tf32.tf32.f32 "                           \
        "{%0,%1,%2,%3},{%4,%5,%6,%7},{%8,%9},{%0,%1,%2,%3};"                            \
        : "+f"(ACC[0]), "+f"(ACC[1]), "+f"(ACC[2]), "+f"(ACC[3])                        \
        : "r"(AL0), "r"(AL1), "r"(AL2), "r"(AL3), "r"(BH0), "r"(BH1));

// ---------------- init: zero scatter buffers, deg = 1 (self-loop) ----------------
__global__ void k_init() {
    int i = blockIdx.x * blockDim.x + threadIdx.x;
    float4 z = make_float4(0.f, 0.f, 0.f, 0.f);
    if (i < NN * 16) ((float4*)g_t1)[i] = z;
    if (i < NN * 8)  ((float4*)g_t2)[i] = z;
    if (i < NN)      g_deg[i] = 1.0f;
}

__global__ void k_deg(const int* __restrict__ ei) {
    int e = blockIdx.x * blockDim.x + threadIdx.x;
    if (e < NE) atomicAdd(&g_deg[ei[NE + e]], 1.0f);
}

__global__ void k_dis() {
    int i = blockIdx.x * blockDim.x + threadIdx.x;
    if (i < NN) g_dis[i] = rsqrtf(g_deg[i]);
}

// ============ k_nfc_tc (R10 proven, byte-identical): h0 = elu(x @ nfc_w^T + nfc_b) ============
__global__ __launch_bounds__(128) void k_nfc_tc(const float* __restrict__ x,
                                                const float* __restrict__ w,
                                                const float* __restrict__ b) {
    constexpr int K = 64, KT = 8, NT = 16;
    __shared__ float sA[64 * 64];            // 16384 B
    __shared__ float2 sW[NT * KT * 32];      // 32768 B  -> 49152 B total static

    int tid = threadIdx.x;
    int base = blockIdx.x * 64;

    for (int i = tid; i < 64 * 16; i += 128) {
        int r = i >> 4, c = i & 15;
        int node = base + r; if (node >= NN) node = NN - 1;
        float4 v = __ldg((const float4*)(x + (size_t)node * K) + c);
        *(float4*)(sA + r * 64 + ((c ^ (r & 15)) << 2)) = v;
    }
    for (int i = tid; i < NT * KT * 32; i += 128) {
        int nt = i >> 8;
        int kt = (i >> 5) & 7;
        int t = i & 31;
        int g = t >> 2, q = t & 3;
        int n = nt * 8 + g;
        sW[(nt * KT + kt) * 32 + t] =
            make_float2(__ldg(w + n * K + kt * 8 + q), __ldg(w + n * K + kt * 8 + q + 4));
    }
    __syncthreads();

    int wid = tid >> 5, lane = tid & 31;
    int g = lane >> 2, q = lane & 3;
    int r0 = wid * 16 + g;
    int r1 = r0 + 8;
    int n0 = base + r0;
    int n1 = base + r1;
    bool v0 = n0 < NN, v1 = n1 < NN;

#pragma unroll 1
    for (int ng = 0; ng < 4; ++ng) {
        float acc[4][4];
#pragma unroll
        for (int j = 0; j < 4; ++j) {
            int col = (ng * 4 + j) * 8 + 2 * q;
            float b0 = __ldg(b + col);
            float b1 = __ldg(b + col + 1);
            acc[j][0] = b0; acc[j][1] = b1; acc[j][2] = b0; acc[j][3] = b1;
        }
#pragma unroll
        for (int kt = 0; kt < KT; ++kt) {
            float a0 = sA[r0 * 64 + (((2 * kt)     ^ (r0 & 15)) << 2) + q];
            float a1 = sA[r1 * 64 + (((2 * kt)     ^ (r1 & 15)) << 2) + q];
            float a2 = sA[r0 * 64 + (((2 * kt + 1) ^ (r0 & 15)) << 2) + q];
            float a3 = sA[r1 * 64 + (((2 * kt + 1) ^ (r1 & 15)) << 2) + q];
            uint32_t ah0 = f2tf32(a0), al0 = f2tf32(a0 - u2f(ah0));
            uint32_t ah1 = f2tf32(a1), al1 = f2tf32(a1 - u2f(ah1));
            uint32_t ah2 = f2tf32(a2), al2 = f2tf32(a2 - u2f(ah2));
            uint32_t ah3 = f2tf32(a3), al3 = f2tf32(a3 - u2f(ah3));
#pragma unroll
            for (int j = 0; j < 4; ++j) {
                float2 bb = sW[((ng * 4 + j) * KT + kt) * 32 + lane];
                uint32_t bh0 = f2tf32(bb.x), bl0 = f2tf32(bb.x - u2f(f2tf32(bb.x)));
                uint32_t bh1 = f2tf32(bb.y), bl1 = f2tf32(bb.y - u2f(f2tf32(bb.y)));
                MMA3(acc[j], ah0, ah1, ah2, ah3, al0, al1, al2, al3, bh0, bh1, bl0, bl1)
            }
        }
#pragma unroll
        for (int j = 0; j < 4; ++j) {
            int col = (ng * 4 + j) * 8 + 2 * q;
            if (v0) *(float2*)(g_h0 + (size_t)n0 * 128 + col) =
                make_float2(elu_f(acc[j][0]), elu_f(acc[j][1]));
            if (v1) *(float2*)(g_h0 + (size_t)n1 * 128 + col) =
                make_float2(elu_f(acc[j][2]), elu_f(acc[j][3]));
        }
    }
}

// ---------------- proj1 (R6/R10 proven): c1 = dis*(h0@bases1^T)[64], w1 = h0@comb1^T+cb[32] ----------------
__global__ __launch_bounds__(128) void k_proj1(const float* __restrict__ bw,
                                               const float* __restrict__ cw,
                                               const float* __restrict__ cb) {
    __shared__ float Ws[96 * 128];  // 48KB
    for (int i = threadIdx.x; i < 64 * 128; i += 128) Ws[i] = bw[i];
    for (int i = threadIdx.x; i < 32 * 128; i += 128) Ws[64 * 128 + i] = cw[i];
    __syncthreads();
    int n0 = blockIdx.x * 256 + threadIdx.x;
    int n1 = n0 + 128;
    bool v1 = n1 < NN;
    if (n0 >= NN) return;
    if (!v1) n1 = n0;
    const float4* xp0 = (const float4*)(g_h0 + (size_t)n0 * 128);
    const float4* xp1 = (const float4*)(g_h0 + (size_t)n1 * 128);
    float d0 = g_dis[n0], d1 = g_dis[n1];
#pragma unroll 1
    for (int oc = 0; oc < 6; ++oc) {
        float acc[2][16];
#pragma unroll
        for (int o = 0; o < 16; ++o) {
            float bb = (oc < 4) ? 0.f : __ldg(cb + (oc - 4) * 16 + o);
            acc[0][o] = bb; acc[1][o] = bb;
        }
#pragma unroll 4
        for (int kc = 0; kc < 32; ++kc) {
            float4 x0 = __ldg(xp0 + kc);
            float4 x1 = __ldg(xp1 + kc);
#pragma unroll
            for (int o = 0; o < 16; ++o) {
                float4 wv = *(const float4*)&Ws[(oc * 16 + o) * 128 + kc * 4];
                acc[0][o] = fmaf(x0.x, wv.x, acc[0][o]);
                acc[0][o] = fmaf(x0.y, wv.y, acc[0][o]);
                acc[0][o] = fmaf(x0.z, wv.z, acc[0][o]);
                acc[0][o] = fmaf(x0.w, wv.w, acc[0][o]);
                acc[1][o] = fmaf(x1.x, wv.x, acc[1][o]);
                acc[1][o] = fmaf(x1.y, wv.y, acc[1][o]);
                acc[1][o] = fmaf(x1.z, wv.z, acc[1][o]);
                acc[1][o] = fmaf(x1.w, wv.w, acc[1][o]);
            }
        }
        if (oc < 4) {
            float* o0 = g_c1 + (size_t)n0 * 64 + oc * 16;
            float* o1 = g_c1 + (size_t)n1 * 64 + oc * 16;
#pragma unroll
            for (int o = 0; o < 16; ++o) o0[o] = d0 * acc[0][o];
            if (v1) {
#pragma unroll
                for (int o = 0; o < 16; ++o) o1[o] = d1 * acc[1][o];
            }
        } else {
            float* o0 = g_w1 + (size_t)n0 * 32 + (oc - 4) * 16;
            float* o1 = g_w1 + (size_t)n1 * 32 + (oc - 4) * 16;
#pragma unroll
            for (int o = 0; o < 16; ++o) o0[o] = acc[0][o];
            if (v1) {
#pragma unroll
                for (int o = 0; o < 16; ++o) o1[o] = acc[1][o];
            }
        }
    }
}

// ---------------- proj2 (R6/R10 proven): c2 = dis*(h1@bases2^T)[32], w2 = h1@comb2^T+cb[32] ----------------
__global__ __launch_bounds__(128) void k_proj2(const float* __restrict__ bw,
                                               const float* __restrict__ cw,
                                               const float* __restrict__ cb) {
    __shared__ float Ws[64 * 128];  // 32KB
    for (int i = threadIdx.x; i < 32 * 128; i += 128) Ws[i] = bw[i];
    for (int i = threadIdx.x; i < 32 * 128; i += 128) Ws[32 * 128 + i] = cw[i];
    __syncthreads();
    int n0 = blockIdx.x * 256 + threadIdx.x;
    int n1 = n0 + 128;
    bool v1 = n1 < NN;
    if (n0 >= NN) return;
    if (!v1) n1 = n0;
    const float4* xp0 = (const float4*)(g_h1 + (size_t)n0 * 128);
    const float4* xp1 = (const float4*)(g_h1 + (size_t)n1 * 128);
    float d0 = g_dis[n0], d1 = g_dis[n1];
#pragma unroll 1
    for (int oc = 0; oc < 4; ++oc) {
        float acc[2][16];
#pragma unroll
        for (int o = 0; o < 16; ++o) {
            float bb = (oc < 2) ? 0.f : __ldg(cb + (oc - 2) * 16 + o);
            acc[0][o] = bb; acc[1][o] = bb;
        }
#pragma unroll 4
        for (int kc = 0; kc < 32; ++kc) {
            float4 x0 = __ldg(xp0 + kc);
            float4 x1 = __ldg(xp1 + kc);
#pragma unroll
            for (int o = 0; o < 16; ++o) {
                float4 wv = *(const float4*)&Ws[(oc * 16 + o) * 128 + kc * 4];
                acc[0][o] = fmaf(x0.x, wv.x, acc[0][o]);
                acc[0][o] = fmaf(x0.y, wv.y, acc[0][o]);
                acc[0][o] = fmaf(x0.z, wv.z, acc[0][o]);
                acc[0][o] = fmaf(x0.w, wv.w, acc[0][o]);
                acc[1][o] = fmaf(x1.x, wv.x, acc[1][o]);
                acc[1][o] = fmaf(x1.y, wv.y, acc[1][o]);
                acc[1][o] = fmaf(x1.z, wv.z, acc[1][o]);
                acc[1][o] = fmaf(x1.w, wv.w, acc[1][o]);
            }
        }
        if (oc < 2) {
            float* o0 = g_c2 + (size_t)n0 * 32 + oc * 16;
            float* o1 = g_c2 + (size_t)n1 * 32 + oc * 16;
#pragma unroll
            for (int o = 0; o < 16; ++o) o0[o] = d0 * acc[0][o];
            if (v1) {
#pragma unroll
                for (int o = 0; o < 16; ++o) o1[o] = d1 * acc[1][o];
            }
        } else {
            float* o0 = g_w2 + (size_t)n0 * 32 + (oc - 2) * 16;
            float* o1 = g_w2 + (size_t)n1 * 32 + (oc - 2) * 16;
#pragma unroll
            for (int o = 0; o < 16; ++o) o0[o] = acc[0][o];
            if (v1) {
#pragma unroll
                for (int o = 0; o < 16; ++o) o1[o] = acc[1][o];
            }
        }
    }
}

// ---------------- edge scatter: t[dst] += c[src]  (vector L2 atomics) ----------------
// 2 float4 quarters per thread: index pair loaded once, reused.
__device__ __forceinline__ void red_add_v4(float4* p, float4 v) {
    asm volatile("red.global.add.v4.f32 [%0], {%1, %2, %3, %4};"
                 :: "l"(p), "f"(v.x), "f"(v.y), "f"(v.z), "f"(v.w) : "memory");
}

__global__ void k_scatter1(const int* __restrict__ ei) {
    int idx = blockIdx.x * blockDim.x + threadIdx.x;  // NE*8 tasks
    if (idx >= NE * 8) return;
    int e = idx >> 3, h = idx & 7;
    int s = __ldg(ei + e);
    int d = __ldg(ei + NE + e);
    float4 va = __ldg((const float4*)g_c1 + (size_t)s * 16 + h);
    float4 vb = __ldg((const float4*)g_c1 + (size_t)s * 16 + h + 8);
    red_add_v4((float4*)g_t1 + (size_t)d * 16 + h, va);
    red_add_v4((float4*)g_t1 + (size_t)d * 16 + h + 8, vb);
}

__global__ void k_scatter2(const int* __restrict__ ei) {
    int idx = blockIdx.x * blockDim.x + threadIdx.x;  // NE*4 tasks
    if (idx >= NE * 4) return;
    int e = idx >> 2, h = idx & 3;
    int s = __ldg(ei + e);
    int d = __ldg(ei + NE + e);
    float4 va = __ldg((const float4*)g_c2 + (size_t)s * 8 + h);
    float4 vb = __ldg((const float4*)g_c2 + (size_t)s * 8 + h + 4);
    red_add_v4((float4*)g_t2 + (size_t)d * 8 + h, va);
    red_add_v4((float4*)g_t2 + (size_t)d * 8 + h + 4, vb);
}

// ---------------- combine conv1: h1 = elu(einsum(w1, dis*(t1+c1)) + bias) ----------------
__global__ __launch_bounds__(128) void k_comb1(const float* __restrict__ bias) {
    int node = blockIdx.x * 128 + threadIdx.x;
    if (node >= NN) return;
    float d = g_dis[node];
    float agg[64];
#pragma unroll
    for (int i = 0; i < 16; ++i) {
        float4 tv = ((const float4*)g_t1)[(size_t)node * 16 + i];
        float4 cv = ((const float4*)g_c1)[(size_t)node * 16 + i];
        agg[4 * i + 0] = d * (tv.x + cv.x);
        agg[4 * i + 1] = d * (tv.y + cv.y);
        agg[4 * i + 2] = d * (tv.z + cv.z);
        agg[4 * i + 3] = d * (tv.w + cv.w);
    }
    float wv[32];
#pragma unroll
    for (int i = 0; i < 8; ++i) {
        float4 v = ((const float4*)g_w1)[(size_t)node * 8 + i];
        wv[4 * i] = v.x; wv[4 * i + 1] = v.y; wv[4 * i + 2] = v.z; wv[4 * i + 3] = v.w;
    }
    float* outp = g_h1 + (size_t)node * 128;
#pragma unroll
    for (int h = 0; h < 8; ++h) {
#pragma unroll
        for (int f = 0; f < 16; ++f) {
            float s = wv[h * 4 + 0] * agg[f]
                    + wv[h * 4 + 1] * agg[16 + f]
                    + wv[h * 4 + 2] * agg[32 + f]
                    + wv[h * 4 + 3] * agg[48 + f];
            outp[h * 16 + f] = elu_f(s + __ldg(bias + h * 16 + f));
        }
    }
}

// ---------------- combine conv2 + ELU + L2 normalize -> hout ----------------
__global__ __launch_bounds__(128) void k_comb2(const float* __restrict__ bias,
                                               float* __restrict__ hout) {
    int node = blockIdx.x * 128 + threadIdx.x;
    if (node >= NN) return;
    float d = g_dis[node];
    float agg[32];
#pragma unroll
    for (int i = 0; i < 8; ++i) {
        float4 tv = ((const float4*)g_t2)[(size_t)node * 8 + i];
        float4 cv = ((const float4*)g_c2)[(size_t)node * 8 + i];
        agg[4 * i + 0] = d * (tv.x + cv.x);
        agg[4 * i + 1] = d * (tv.y + cv.y);
        agg[4 * i + 2] = d * (tv.z + cv.z);
        agg[4 * i + 3] = d * (tv.w + cv.w);
    }
    float wv[32];
#pragma unroll
    for (int i = 0; i < 8; ++i) {
        float4 v = ((const float4*)g_w2)[(size_t)node * 8 + i];
        wv[4 * i] = v.x; wv[4 * i + 1] = v.y; wv[4 * i + 2] = v.z; wv[4 * i + 3] = v.w;
    }
    float tmp[64];
    float ss = 0.f;
#pragma unroll
    for (int h = 0; h < 8; ++h) {
#pragma unroll
        for (int f = 0; f < 8; ++f) {
            float s = wv[h * 4 + 0] * agg[f]
                    + wv[h * 4 + 1] * agg[8 + f]
                    + wv[h * 4 + 2] * agg[16 + f]
                    + wv[h * 4 + 3] * agg[24 + f];
            float v = elu_f(s + __ldg(bias + h * 8 + f));
            tmp[h * 8 + f] = v;
            ss = fmaf(v, v, ss);
        }
    }
    float sc = 1.0f / fmaxf(sqrtf(ss), 1e-12f);
    float4* op = (float4*)(hout + (size_t)node * 64);
#pragma unroll
    for (int i = 0; i < 16; ++i)
        op[i] = make_float4(tmp[4 * i] * sc, tmp[4 * i + 1] * sc,
                            tmp[4 * i + 2] * sc, tmp[4 * i + 3] * sc);
}

// ---------------- fused per-graph: sum-pool, attention softmax, z_a, z_c ----------------
__global__ __launch_bounds__(128) void k_graph(const float* __restrict__ h,
                                               const float* __restrict__ z_e,
                                               const float* __restrict__ aw,
                                               const float* __restrict__ ab,
                                               const float* __restrict__ fcg_w,
                                               const float* __restrict__ fcg_b,
                                               const float* __restrict__ fccg_w,
                                               const float* __restrict__ fccg_b,
                                               float* __restrict__ za,
                                               float* __restrict__ zc) {
    int g = blockIdx.x;
    int t = threadIdx.x;
    __shared__ float sh[100 * 64];
    __shared__ float slog[100];
    __shared__ float sred[4];
    __shared__ float sp_hs[128];
    __shared__ float sp_zc[128];
    __shared__ float szdot, sm, sdenom;

    const float* hg = h + (size_t)g * 100 * 64;
    for (int i = t; i < 6400; i += 128) sh[i] = hg[i];

    if (t < 32) {
        float v = __ldg(z_e + g * 32 + t) * __ldg(aw + 64 + t);
#pragma unroll
        for (int o = 16; o; o >>= 1) v += __shfl_xor_sync(0xffffffff, v, o);
        if (t == 0) szdot = v;
    }
    __syncthreads();

    int w = t >> 5, l = t & 31;
    {
        float a0 = __ldg(aw + l);
        float a1 = __ldg(aw + 32 + l);
        float bb = __ldg(ab);
        for (int n = w; n < 100; n += 4) {
            float p = sh[n * 64 + l] * a0 + sh[n * 64 + 32 + l] * a1;
#pragma unroll
            for (int o = 16; o; o >>= 1) p += __shfl_xor_sync(0xffffffff, p, o);
            if (l == 0) slog[n] = p + szdot + bb + 1e-16f;
        }
    }
    __syncthreads();

    float m = -INFINITY;
    if (t < 100) m = slog[t];
#pragma unroll
    for (int o = 16; o; o >>= 1) m = fmaxf(m, __shfl_xor_sync(0xffffffff, m, o));
    if (l == 0) sred[w] = m;
    __syncthreads();
    if (t == 0) sm = fmaxf(fmaxf(sred[0], sred[1]), fmaxf(sred[2], sred[3]));
    __syncthreads();

    float ssum = 0.f;
    if (t < 100) {
        float e = expf(slog[t] - sm);
        slog[t] = e;
        ssum = e;
    }
#pragma unroll
    for (int o = 16; o; o >>= 1) ssum += __shfl_xor_sync(0xffffffff, ssum, o);
    if (l == 0) sred[w] = ssum;
    __syncthreads();
    if (t == 0) sdenom = sred[0] + sred[1] + sred[2] + sred[3] + 1e-16f;
    __syncthreads();

    float inv = 1.0f / sdenom;
    int f = t & 63, half = t >> 6;
    float hs = 0.f, zcv = 0.f;
    for (int n = half * 50; n < half * 50 + 50; ++n) {
        float hv = sh[n * 64 + f];
        hs += hv;
        zcv = fmaf(slog[n], hv, zcv);
    }
    sp_hs[t] = hs;
    sp_zc[t] = zcv * inv;
    __syncthreads();
    if (t < 64) {
        sp_hs[t] = sp_hs[t] + sp_hs[t + 64];
        sp_zc[t] = sp_zc[t] + sp_zc[t + 64];
    }
    __syncthreads();

    if (t < 64) {
        float acc = __ldg(fcg_b + t);
        const float* wr = fcg_w + t * 64;
#pragma unroll 8
        for (int k = 0; k < 64; ++k) acc = fmaf(sp_hs[k], __ldg(wr + k), acc);
        za[(size_t)g * 64 + t] = acc;
    } else {
        int ff = t - 64;
        float acc = __ldg(fccg_b + ff);
        const float* wr = fccg_w + ff * 64;
#pragma unroll 8
        for (int k = 0; k < 64; ++k) acc = fmaf(sp_zc[k], __ldg(wr + k), acc);
        zc[(size_t)g * 64 + ff] = acc;
    }
}

// ---------------- launch ----------------
extern "C" void kernel_launch(void* const* d_in, const int* in_sizes, int n_in,
                              void* d_out, int out_size) {
    const float* x        = (const float*)d_in[0];
    const int*   ei       = (const int*)d_in[1];
    const float* z_e      = (const float*)d_in[4];
    const float* nfc_w    = (const float*)d_in[5];
    const float* nfc_b    = (const float*)d_in[6];
    const float* gc1_bw   = (const float*)d_in[7];
    const float* gc1_cw   = (const float*)d_in[8];
    const float* gc1_cb   = (const float*)d_in[9];
    const float* gc1_bias = (const float*)d_in[10];
    const float* gc2_bw   = (const float*)d_in[11];
    const float* gc2_cw   = (const float*)d_in[12];
    const float* gc2_cb   = (const float*)d_in[13];
    const float* gc2_bias = (const float*)d_in[14];
    const float* attn_w   = (const float*)d_in[15];
    const float* attn_b   = (const float*)d_in[16];
    const float* fcg_w    = (const float*)d_in[17];
    const float* fcg_b    = (const float*)d_in[18];
    const float* fccg_w   = (const float*)d_in[19];
    const float* fccg_b   = (const float*)d_in[20];

    float* out   = (float*)d_out;
    float* za    = out;
    float* zc    = out + NG * 64;
    float* hout  = out + 2 * NG * 64;

    int gemmBlocks = (NN + 255) / 256;   // 391, 2 nodes/thread (proj kernels)
    int tcBlocks   = (NN + 63) / 64;     // 1563, 64 nodes/block (tc nfc)
    int nodeBlocks = (NN + 127) / 128;

    k_init<<<(NN * 16 + 255) / 256, 256>>>();
    k_deg<<<(NE + 255) / 256, 256>>>(ei);
    k_dis<<<(NN + 255) / 256, 256>>>();
    k_nfc_tc<<<tcBlocks, 128>>>(x, nfc_w, nfc_b);
    k_proj1<<<gemmBlocks, 128>>>(gc1_bw, gc1_cw, gc1_cb);
    k_scatter1<<<(NE * 8) / 256, 256>>>(ei);
    k_comb1<<<nodeBlocks, 128>>>(gc1_bias);
    k_proj2<<<gemmBlocks, 128>>>(gc2_bw, gc2_cw, gc2_cb);
    k_scatter2<<<(NE * 4) / 256, 256>>>(ei);
    k_comb2<<<nodeBlocks, 128>>>(gc2_bias, hout);
    k_graph<<<NG, 128>>>(hout, z_e, attn_w, attn_b, fcg_w, fcg_b,
                         fccg_w, fccg_b, za, zc);
}